// round 16
// baseline (speedup 1.0000x reference)
#include <cuda_runtime.h>

#define TT 512
#define BB 1024
#define NN 64
#define GRID 512      // main kernel: one pair (2 batches) per 64-thread CTA
#define LGRID 128     // len/pair kernel CTAs (4 rows each)

__device__ float g_partial[BB];
__device__ int g_len[BB];
__device__ int g_lenpart[LGRID][BB];
__device__ int g_pairs[2][BB / 2];
__device__ int g_count = 0;
__device__ int g_count2 = 0;

typedef unsigned long long ull;

// ---- packed f32x2 helpers (Blackwell) ----
__device__ __forceinline__ ull pack2(float x, float y) {
    ull r; asm("mov.b64 %0, {%1, %2};" : "=l"(r) : "f"(x), "f"(y)); return r;
}
__device__ __forceinline__ void unpack2(ull v, float& x, float& y) {
    asm("mov.b64 {%0, %1}, %2;" : "=f"(x), "=f"(y) : "l"(v));
}
__device__ __forceinline__ ull fma2(ull a, ull b, ull c) {
    ull d; asm("fma.rn.f32x2 %0, %1, %2, %3;" : "=l"(d) : "l"(a), "l"(b), "l"(c)); return d;
}
__device__ __forceinline__ ull add2(ull a, ull b) {
    ull d; asm("add.rn.f32x2 %0, %1, %2;" : "=l"(d) : "l"(a), "l"(b)); return d;
}

__device__ __forceinline__ void cp_async4(unsigned smem_addr, const void* gptr) {
    asm volatile("cp.async.ca.shared.global [%0], [%1], 4;" :: "r"(smem_addr), "l"(gptr));
}
__device__ __forceinline__ void cp_commit() {
    asm volatile("cp.async.commit_group;");
}
__device__ __forceinline__ void cp_wait1() {
    asm volatile("cp.async.wait_group 1;");
}
__device__ __forceinline__ void cp_wait0() {
    asm volatile("cp.async.wait_group 0;");
}

// --- kernel 1: mask column sums + last-CTA counting sort & complement pairing ---
__global__ void __launch_bounds__(256) len_pair_kernel(const void* __restrict__ mask_raw) {
    const int tid = threadIdx.x;
    const int c = blockIdx.x;                  // rows [4c, 4c+4)

    const unsigned char* m8 = (const unsigned char*)mask_raw;
    const int* m32 = (const int*)mask_raw;
    const float* mf = (const float*)mask_raw;
    int mmode;  // 0 = u8, 1 = i32, 2 = f32 (mask row 0 all-True since lengths >= 1)
    if (m8[0] == 1 && m8[1] == 1)      mmode = 0;
    else if (m8[0] == 1)               mmode = 1;
    else                               mmode = 2;

    int acc0 = 0, acc1 = 0, acc2 = 0, acc3 = 0;
#pragma unroll
    for (int r = 0; r < 4; r++) {
        const int row = c * 4 + r;
        if (mmode == 1) {
            acc0 += (m32[row * BB + tid]       != 0);
            acc1 += (m32[row * BB + tid + 256] != 0);
            acc2 += (m32[row * BB + tid + 512] != 0);
            acc3 += (m32[row * BB + tid + 768] != 0);
        } else if (mmode == 0) {
            acc0 += (m8[row * BB + tid]       != 0);
            acc1 += (m8[row * BB + tid + 256] != 0);
            acc2 += (m8[row * BB + tid + 512] != 0);
            acc3 += (m8[row * BB + tid + 768] != 0);
        } else {
            acc0 += (mf[row * BB + tid]       != 0.0f);
            acc1 += (mf[row * BB + tid + 256] != 0.0f);
            acc2 += (mf[row * BB + tid + 512] != 0.0f);
            acc3 += (mf[row * BB + tid + 768] != 0.0f);
        }
    }
    g_lenpart[c][tid]       = acc0;
    g_lenpart[c][tid + 256] = acc1;
    g_lenpart[c][tid + 512] = acc2;
    g_lenpart[c][tid + 768] = acc3;

    // last CTA: finalize lengths, counting-sort by length, complement pairing
    __shared__ int islast;
    __shared__ int hist[TT + 1];
    __threadfence();
    __syncthreads();
    if (tid == 0)
        islast = (atomicAdd(&g_count2, 1) == LGRID - 1);
    __syncthreads();
    if (!islast) return;
    __threadfence();

    for (int i = tid; i <= TT; i += 256) hist[i] = 0;
    __syncthreads();
#pragma unroll
    for (int j = 0; j < 4; j++) {
        const int b = tid + j * 256;
        int len = 0;
#pragma unroll 16
        for (int cc = 0; cc < LGRID; cc++) len += g_lenpart[cc][b];
        g_len[b] = len;
        atomicAdd(&hist[len], 1);
    }
    __syncthreads();
    if (tid == 0) {                            // serial exclusive prefix (513 bins)
        int run = 0;
        for (int l = 0; l <= TT; l++) { int h = hist[l]; hist[l] = run; run += h; }
        g_count2 = 0;                          // reset for next graph replay
    }
    __syncthreads();
#pragma unroll
    for (int j = 0; j < 4; j++) {
        const int b = tid + j * 256;
        int pos = atomicAdd(&hist[g_len[b]], 1);   // ascending rank (ties any order)
        if (pos < BB / 2) g_pairs[0][pos] = b;          // short half
        else              g_pairs[1][BB - 1 - pos] = b; // complement long half
    }
}

// ---------------- kernel 2: fused forward + score + reduce ----------------
__global__ void __launch_bounds__(64, 4) crf_fused_kernel(
    const float* __restrict__ emit,
    const float* __restrict__ trans,
    const float* __restrict__ strans,
    const float* __restrict__ etrans,
    const void* __restrict__ target_raw,
    float* __restrict__ out)
{
    const int tid = threadIdx.x;          // 0..63
    const int lane = tid & 31;
    const int w = tid >> 5;
    const int k = tid;                    // this lane's state (0..63)
    const int pairid = blockIdx.x;

    __shared__ __align__(16) float vbuf[2][NN];   // double-buffered state exchange
    __shared__ float stagef[2][8][32];            // 8-slot cp.async ring per warp
    __shared__ float wred[2], sred[2];

    const int* t32p = (const int*)target_raw;
    int oddbits = 0;
#pragma unroll
    for (int i = 1; i < 16; i += 2) oddbits |= t32p[i];
    const int tmode = (oddbits == 0) ? 1 : 0;  // 1 = int64, 0 = int32
    const long long* t64p = (const long long*)target_raw;

    // E column for this lane's state, packed over j-pairs (64 regs)
    ull Ecol[32];
#pragma unroll
    for (int p = 0; p < 32; p++) {
        float t0 = trans[(2 * p) * NN + k];
        float t1 = trans[(2 * p + 1) * NN + k];
        Ecol[p] = pack2(__expf(t0), __expf(t1));
    }

    const unsigned stg0 = (unsigned)__cvta_generic_to_shared(&stagef[w][0][lane]);
#define STG(SLOT) (stg0 + (unsigned)(SLOT) * 128u)
#define LDSTAGE(DST, SLOT) \
    asm volatile("ld.shared.f32 %0, [%1];" : "=f"(DST) : "r"(STG(SLOT)))

    const float eet = __expf(etrans[k]);

// One forward step. EM = pre-exponentiated emission (computed off-chain at block top).
// NORM: apply 2^-s normalization (lag-1 ref read free from vv[0]).
#define STEP_BODY(EM, PAR, NORM)                                                \
    {                                                                           \
        vbuf[PAR][k] = v;                                                       \
        __syncthreads();                                                        \
        const ulonglong2* vv = reinterpret_cast<const ulonglong2*>(vbuf[PAR]);  \
        ulonglong2 q0 = vv[0];                                                  \
        float m;                                                                \
        if (NORM) {                                                             \
            float rref, hi_; unpack2(q0.x, rref, hi_); (void)hi_;               \
            int sexp = ((__float_as_int(rref) >> 23) & 0xFF) - 127;             \
            stotal += sexp;                                                     \
            float scl = __int_as_float((127 - sexp) << 23);                     \
            m = (EM) * scl;                                                     \
        } else {                                                                \
            m = (EM);                                                           \
        }                                                                       \
        ull c0 = 0, c1 = 0, c2 = 0, c3 = 0;                                     \
        {                                                                       \
            ulonglong2 q1 = vv[1];                                              \
            c0 = fma2(q0.x, Ecol[0], c0);                                       \
            c1 = fma2(q0.y, Ecol[1], c1);                                       \
            c2 = fma2(q1.x, Ecol[2], c2);                                       \
            c3 = fma2(q1.y, Ecol[3], c3);                                       \
        }                                                                       \
        _Pragma("unroll")                                                       \
        for (int p = 4; p < 32; p += 4) {                                       \
            ulonglong2 u0 = vv[p / 2], u1 = vv[p / 2 + 1];                      \
            c0 = fma2(u0.x, Ecol[p],     c0);                                   \
            c1 = fma2(u0.y, Ecol[p + 1], c1);                                   \
            c2 = fma2(u1.x, Ecol[p + 2], c2);                                   \
            c3 = fma2(u1.y, Ecol[p + 3], c3);                                   \
        }                                                                       \
        float cx, cy;                                                           \
        unpack2(add2(add2(c0, c1), add2(c2, c3)), cx, cy);                      \
        v = (cx + cy) * m;                                                      \
    }

    for (int ph = 0; ph < 2; ph++) {
        const int b = g_pairs[ph][pairid];
        const int len = g_len[b];
        const float* bp = emit + b * NN + k;     // row stride = BB*NN floats

        // init: alpha(0)_k = strans[k] + emit[0][b][k]; offset C0 = alpha(0)_0
        const float C0 = strans[0] + emit[b * NN];
        float v = __expf(strans[k] + bp[0] - C0);
        int stotal = 0;

        cp_wait0();                              // drain ring before reuse
        __syncthreads();
        // prologue: G0 = steps 1..4 (slots 0..3), G1 = steps 5..8 (slots 4..7)
#pragma unroll
        for (int j = 0; j < 4; j++)
            cp_async4(STG(j), bp + (size_t)min(1 + j, TT - 1) * (BB * NN));
        cp_commit();
#pragma unroll
        for (int j = 0; j < 4; j++)
            cp_async4(STG(4 + j), bp + (size_t)min(5 + j, TT - 1) * (BB * NN));
        cp_commit();

        int pb = 0;                              // ring half being consumed
        int t = 1;
        for (; t + 4 <= len; t += 4) {           // t odd: parities 1,0,1,0
            cp_wait1();                          // current half's group complete
            const int ro = pb << 2;
            // batch-load + pre-exponentiate the whole block's emissions (off-chain)
            float e0, e1, e2, e3;
            LDSTAGE(e0, ro + 0); LDSTAGE(e1, ro + 1);
            LDSTAGE(e2, ro + 2); LDSTAGE(e3, ro + 3);
            float em0 = __expf(e0), em1 = __expf(e1);
            float em2 = __expf(e2), em3 = __expf(e3);
            STEP_BODY(em0, 1, true);
            STEP_BODY(em1, 0, false);
            STEP_BODY(em2, 1, false);
            STEP_BODY(em3, 0, false);
            // refill freed half with steps t+8..t+11
#pragma unroll
            for (int j = 0; j < 4; j++)
                cp_async4(STG(ro + j), bp + (size_t)min(t + 8 + j, TT - 1) * (BB * NN));
            cp_commit();
            pb ^= 1;
        }
        cp_wait0();
        for (; t < len; t++) {                   // tail: data already staged
            const int slot = (t - 1) & 7, par = t & 1;
            float e; LDSTAGE(e, slot);
            float em = __expf(e);
            STEP_BODY(em, par, true);
        }

        // logZ partial
        float wpart = v * eet;
#pragma unroll
        for (int o = 16; o; o >>= 1) wpart += __shfl_xor_sync(0xffffffffu, wpart, o);

        // gold score: 64-lane strided over timesteps
        float sc = 0.f;
        for (int i = tid; i < len; i += 64) {
            size_t idx = (size_t)i * BB + b;
            int tg = tmode ? (int)t64p[idx] : t32p[idx];
            sc += emit[idx * NN + tg];
            if (i > 0) {
                size_t p = (size_t)(i - 1) * BB + b;
                int pg = tmode ? (int)t64p[p] : t32p[p];
                sc += trans[pg * NN + tg];
            }
        }
#pragma unroll
        for (int o = 16; o; o >>= 1) sc += __shfl_xor_sync(0xffffffffu, sc, o);

        if (lane == 0) { wred[w] = wpart; sred[w] = sc; }
        __syncthreads();
        if (tid == 0) {
            float wsum = wred[0] + wred[1];
            float logZ = C0 + 0.6931471805599453f * (float)stotal + __logf(wsum);
            int tg0 = tmode ? (int)t64p[b] : t32p[b];
            size_t li = (size_t)(len - 1) * BB + b;
            int tgl = tmode ? (int)t64p[li] : t32p[li];
            float score = sred[0] + sred[1] + strans[tg0] + etrans[tgl];
            g_partial[b] = logZ - score;
        }
        __syncthreads();
    }
#undef STEP_BODY
#undef LDSTAGE
#undef STG

    // ---- last-CTA-done deterministic reduction ----
    __shared__ float rsh[64];
    __shared__ int islast;
    __threadfence();
    __syncthreads();
    if (tid == 0)
        islast = (atomicAdd(&g_count, 1) == GRID - 1);
    __syncthreads();
    if (islast) {
        __threadfence();
        float s = 0.f;
#pragma unroll
        for (int i = 0; i < BB / 64; i++)       // fixed order: deterministic
            s += g_partial[tid + i * 64];
        rsh[tid] = s;
        __syncthreads();
        for (int off = 32; off > 0; off >>= 1) {
            if (tid < off) rsh[tid] += rsh[tid + off];
            __syncthreads();
        }
        if (tid == 0) {
            out[0] = rsh[0] * (1.0f / BB);
            g_count = 0;                        // reset for next graph replay
        }
    }
}

extern "C" void kernel_launch(void* const* d_in, const int* in_sizes, int n_in,
                              void* d_out, int out_size) {
    const float* emit   = (const float*)d_in[0];
    const float* trans  = (const float*)d_in[1];
    const float* strans = (const float*)d_in[2];
    const float* etrans = (const float*)d_in[3];
    const void* target  = d_in[4];
    const void* mask    = d_in[5];

    len_pair_kernel<<<LGRID, 256>>>(mask);
    crf_fused_kernel<<<GRID, 64>>>(emit, trans, strans, etrans, target,
                                   (float*)d_out);
}

// round 17
// speedup vs baseline: 1.1506x; 1.1506x over previous
#include <cuda_runtime.h>

#define TT 512
#define BB 1024
#define NN 64
#define GRID 512      // main kernel: one pair (2 batches) per 64-thread CTA
#define LGRID 128     // len kernel CTAs (4 rows each)

__device__ float g_partial[BB];
__device__ int g_len[BB];
__device__ int g_lenpart[LGRID][BB];
__device__ int g_pairs[2][BB / 2];
__device__ int g_count = 0;

typedef unsigned long long ull;

// ---- packed f32x2 helpers (Blackwell) ----
__device__ __forceinline__ ull pack2(float x, float y) {
    ull r; asm("mov.b64 %0, {%1, %2};" : "=l"(r) : "f"(x), "f"(y)); return r;
}
__device__ __forceinline__ void unpack2(ull v, float& x, float& y) {
    asm("mov.b64 {%0, %1}, %2;" : "=f"(x), "=f"(y) : "l"(v));
}
__device__ __forceinline__ ull fma2(ull a, ull b, ull c) {
    ull d; asm("fma.rn.f32x2 %0, %1, %2, %3;" : "=l"(d) : "l"(a), "l"(b), "l"(c)); return d;
}
__device__ __forceinline__ ull add2(ull a, ull b) {
    ull d; asm("add.rn.f32x2 %0, %1, %2;" : "=l"(d) : "l"(a), "l"(b)); return d;
}

__device__ __forceinline__ void cp_async4(unsigned smem_addr, const void* gptr) {
    asm volatile("cp.async.ca.shared.global [%0], [%1], 4;" :: "r"(smem_addr), "l"(gptr));
}
__device__ __forceinline__ void cp_commit() {
    asm volatile("cp.async.commit_group;");
}
__device__ __forceinline__ void cp_wait1() {
    asm volatile("cp.async.wait_group 1;");
}
__device__ __forceinline__ void cp_wait0() {
    asm volatile("cp.async.wait_group 0;");
}

// ------- kernel 1: coalesced per-CTA partial column sums of the mask -------
__global__ void __launch_bounds__(256) len_kernel(const void* __restrict__ mask_raw) {
    const int tid = threadIdx.x;
    const int c = blockIdx.x;                  // rows [4c, 4c+4)

    const unsigned char* m8 = (const unsigned char*)mask_raw;
    const int* m32 = (const int*)mask_raw;
    const float* mf = (const float*)mask_raw;
    int mmode;  // 0 = u8, 1 = i32, 2 = f32 (mask row 0 all-True since lengths >= 1)
    if (m8[0] == 1 && m8[1] == 1)      mmode = 0;
    else if (m8[0] == 1)               mmode = 1;
    else                               mmode = 2;

    int acc0 = 0, acc1 = 0, acc2 = 0, acc3 = 0;
#pragma unroll
    for (int r = 0; r < 4; r++) {
        const int row = c * 4 + r;
        if (mmode == 1) {
            acc0 += (m32[row * BB + tid]       != 0);
            acc1 += (m32[row * BB + tid + 256] != 0);
            acc2 += (m32[row * BB + tid + 512] != 0);
            acc3 += (m32[row * BB + tid + 768] != 0);
        } else if (mmode == 0) {
            acc0 += (m8[row * BB + tid]       != 0);
            acc1 += (m8[row * BB + tid + 256] != 0);
            acc2 += (m8[row * BB + tid + 512] != 0);
            acc3 += (m8[row * BB + tid + 768] != 0);
        } else {
            acc0 += (mf[row * BB + tid]       != 0.0f);
            acc1 += (mf[row * BB + tid + 256] != 0.0f);
            acc2 += (mf[row * BB + tid + 512] != 0.0f);
            acc3 += (mf[row * BB + tid + 768] != 0.0f);
        }
    }
    g_lenpart[c][tid]       = acc0;
    g_lenpart[c][tid + 256] = acc1;
    g_lenpart[c][tid + 512] = acc2;
    g_lenpart[c][tid + 768] = acc3;
}

// --- kernel 2: sum partials, COUNTING sort by length, complement pairing ---
__global__ void __launch_bounds__(BB) sort_kernel() {
    __shared__ int hist[TT + 1];     // histogram -> exclusive prefix -> running pos
    __shared__ int scan[BB];         // Hillis-Steele workspace
    const int tid = threadIdx.x;

    int len = 0;
#pragma unroll 16
    for (int c = 0; c < LGRID; c++) len += g_lenpart[c][tid];
    g_len[tid] = len;

    if (tid <= TT) hist[tid] = 0;
    __syncthreads();
    atomicAdd(&hist[len], 1);
    __syncthreads();

    // inclusive scan of hist[0..TT] (padded to BB with zeros), 10 rounds
    scan[tid] = (tid <= TT) ? hist[tid] : 0;
    __syncthreads();
#pragma unroll
    for (int off = 1; off < BB; off <<= 1) {
        int val = (tid >= off) ? scan[tid - off] : 0;
        __syncthreads();
        scan[tid] += val;
        __syncthreads();
    }
    // exclusive prefix back into hist
    if (tid <= TT) hist[tid] = (tid == 0) ? 0 : scan[tid - 1];
    __syncthreads();

    // scatter: ascending rank by length (ties in any order -- pairing-only effect)
    int pos = atomicAdd(&hist[len], 1);
    if (pos < BB / 2) g_pairs[0][pos] = tid;            // short half
    else              g_pairs[1][BB - 1 - pos] = tid;   // complement long half
}

// ---------------- kernel 3: fused forward + score + reduce (round-13 verbatim) ----------------
__global__ void __launch_bounds__(64, 8) crf_fused_kernel(
    const float* __restrict__ emit,
    const float* __restrict__ trans,
    const float* __restrict__ strans,
    const float* __restrict__ etrans,
    const void* __restrict__ target_raw,
    float* __restrict__ out)
{
    const int tid = threadIdx.x;          // 0..63
    const int lane = tid & 31;
    const int w = tid >> 5;
    const int k = tid;                    // this lane's state (0..63)
    const int pairid = blockIdx.x;

    __shared__ __align__(16) float vbuf[2][NN];   // double-buffered state exchange
    __shared__ float stagef[2][8][32];            // 8-slot cp.async ring per warp
    __shared__ float wred[2], sred[2];

    const int* t32p = (const int*)target_raw;
    int oddbits = 0;
#pragma unroll
    for (int i = 1; i < 16; i += 2) oddbits |= t32p[i];
    const int tmode = (oddbits == 0) ? 1 : 0;  // 1 = int64, 0 = int32
    const long long* t64p = (const long long*)target_raw;

    // E column for this lane's state, packed over j-pairs (64 regs)
    ull Ecol[32];
#pragma unroll
    for (int p = 0; p < 32; p++) {
        float t0 = trans[(2 * p) * NN + k];
        float t1 = trans[(2 * p + 1) * NN + k];
        Ecol[p] = pack2(__expf(t0), __expf(t1));
    }

    const unsigned stg0 = (unsigned)__cvta_generic_to_shared(&stagef[w][0][lane]);
#define STG(SLOT) (stg0 + (unsigned)(SLOT) * 128u)
#define LDSTAGE(DST, SLOT) \
    asm volatile("ld.shared.f32 %0, [%1];" : "=f"(DST) : "r"(STG(SLOT)))

    const float eet = __expf(etrans[k]);

// One forward step. NORM: apply 2^-s normalization (lag-1 ref read free from vv[0])
#define STEP_BODY(SLOT, PAR, NORM)                                              \
    {                                                                           \
        float e; LDSTAGE(e, SLOT);                                              \
        vbuf[PAR][k] = v;                                                       \
        __syncthreads();                                                        \
        const ulonglong2* vv = reinterpret_cast<const ulonglong2*>(vbuf[PAR]);  \
        ulonglong2 q0 = vv[0];                                                  \
        float m;                                                                \
        if (NORM) {                                                             \
            float rref, hi_; unpack2(q0.x, rref, hi_); (void)hi_;               \
            int sexp = ((__float_as_int(rref) >> 23) & 0xFF) - 127;             \
            stotal += sexp;                                                     \
            float scl = __int_as_float((127 - sexp) << 23);                     \
            m = __expf(e) * scl;                                                \
        } else {                                                                \
            m = __expf(e);                                                      \
        }                                                                       \
        ull c0 = 0, c1 = 0, c2 = 0, c3 = 0;                                     \
        {                                                                       \
            ulonglong2 q1 = vv[1];                                              \
            c0 = fma2(q0.x, Ecol[0], c0);                                       \
            c1 = fma2(q0.y, Ecol[1], c1);                                       \
            c2 = fma2(q1.x, Ecol[2], c2);                                       \
            c3 = fma2(q1.y, Ecol[3], c3);                                       \
        }                                                                       \
        _Pragma("unroll")                                                       \
        for (int p = 4; p < 32; p += 4) {                                       \
            ulonglong2 u0 = vv[p / 2], u1 = vv[p / 2 + 1];                      \
            c0 = fma2(u0.x, Ecol[p],     c0);                                   \
            c1 = fma2(u0.y, Ecol[p + 1], c1);                                   \
            c2 = fma2(u1.x, Ecol[p + 2], c2);                                   \
            c3 = fma2(u1.y, Ecol[p + 3], c3);                                   \
        }                                                                       \
        float cx, cy;                                                           \
        unpack2(add2(add2(c0, c1), add2(c2, c3)), cx, cy);                      \
        v = (cx + cy) * m;                                                      \
    }

    for (int ph = 0; ph < 2; ph++) {
        const int b = g_pairs[ph][pairid];
        const int len = g_len[b];
        const float* bp = emit + b * NN + k;     // row stride = BB*NN floats

        // init: alpha(0)_k = strans[k] + emit[0][b][k]; offset C0 = alpha(0)_0
        const float C0 = strans[0] + emit[b * NN];
        float v = __expf(strans[k] + bp[0] - C0);
        int stotal = 0;

        cp_wait0();                              // drain ring before reuse
        __syncthreads();
        // prologue: G0 = steps 1..4 (slots 0..3), G1 = steps 5..8 (slots 4..7)
#pragma unroll
        for (int j = 0; j < 4; j++)
            cp_async4(STG(j), bp + (size_t)min(1 + j, TT - 1) * (BB * NN));
        cp_commit();
#pragma unroll
        for (int j = 0; j < 4; j++)
            cp_async4(STG(4 + j), bp + (size_t)min(5 + j, TT - 1) * (BB * NN));
        cp_commit();

        int pb = 0;                              // ring half being consumed
        int t = 1;
        for (; t + 4 <= len; t += 4) {           // t odd: parities 1,0,1,0
            cp_wait1();                          // current half's group complete
            const int ro = pb << 2;
            STEP_BODY(ro + 0, 1, true);
            STEP_BODY(ro + 1, 0, false);
            STEP_BODY(ro + 2, 1, false);
            STEP_BODY(ro + 3, 0, false);
            // refill freed half with steps t+8..t+11
#pragma unroll
            for (int j = 0; j < 4; j++)
                cp_async4(STG(ro + j), bp + (size_t)min(t + 8 + j, TT - 1) * (BB * NN));
            cp_commit();
            pb ^= 1;
        }
        cp_wait0();
        for (; t < len; t++) {                   // tail: data already staged
            const int slot = (t - 1) & 7, par = t & 1;
            STEP_BODY(slot, par, true);
        }

        // logZ partial
        float wpart = v * eet;
#pragma unroll
        for (int o = 16; o; o >>= 1) wpart += __shfl_xor_sync(0xffffffffu, wpart, o);

        // gold score: 64-lane strided over timesteps
        float sc = 0.f;
        for (int i = tid; i < len; i += 64) {
            size_t idx = (size_t)i * BB + b;
            int tg = tmode ? (int)t64p[idx] : t32p[idx];
            sc += emit[idx * NN + tg];
            if (i > 0) {
                size_t p = (size_t)(i - 1) * BB + b;
                int pg = tmode ? (int)t64p[p] : t32p[p];
                sc += trans[pg * NN + tg];
            }
        }
#pragma unroll
        for (int o = 16; o; o >>= 1) sc += __shfl_xor_sync(0xffffffffu, sc, o);

        if (lane == 0) { wred[w] = wpart; sred[w] = sc; }
        __syncthreads();
        if (tid == 0) {
            float wsum = wred[0] + wred[1];
            float logZ = C0 + 0.6931471805599453f * (float)stotal + __logf(wsum);
            int tg0 = tmode ? (int)t64p[b] : t32p[b];
            size_t li = (size_t)(len - 1) * BB + b;
            int tgl = tmode ? (int)t64p[li] : t32p[li];
            float score = sred[0] + sred[1] + strans[tg0] + etrans[tgl];
            g_partial[b] = logZ - score;
        }
        __syncthreads();
    }
#undef STEP_BODY
#undef LDSTAGE
#undef STG

    // ---- last-CTA-done deterministic reduction ----
    __shared__ float rsh[64];
    __shared__ int islast;
    __threadfence();
    __syncthreads();
    if (tid == 0)
        islast = (atomicAdd(&g_count, 1) == GRID - 1);
    __syncthreads();
    if (islast) {
        __threadfence();
        float s = 0.f;
#pragma unroll
        for (int i = 0; i < BB / 64; i++)       // fixed order: deterministic
            s += g_partial[tid + i * 64];
        rsh[tid] = s;
        __syncthreads();
        for (int off = 32; off > 0; off >>= 1) {
            if (tid < off) rsh[tid] += rsh[tid + off];
            __syncthreads();
        }
        if (tid == 0) {
            out[0] = rsh[0] * (1.0f / BB);
            g_count = 0;                        // reset for next graph replay
        }
    }
}

extern "C" void kernel_launch(void* const* d_in, const int* in_sizes, int n_in,
                              void* d_out, int out_size) {
    const float* emit   = (const float*)d_in[0];
    const float* trans  = (const float*)d_in[1];
    const float* strans = (const float*)d_in[2];
    const float* etrans = (const float*)d_in[3];
    const void* target  = d_in[4];
    const void* mask    = d_in[5];

    len_kernel<<<LGRID, 256>>>(mask);
    sort_kernel<<<1, BB>>>();
    crf_fused_kernel<<<GRID, 64>>>(emit, trans, strans, etrans, target,
                                   (float*)d_out);
}